// round 13
// baseline (speedup 1.0000x reference)
#include <cuda_runtime.h>
#include <cuda_fp16.h>
#include <math.h>
#include <stdint.h>

#define HID   2048
#define DOWND 512
#define NE    16
#define NTOK  8192
#define NPAIR (NTOK*2)

// ---------------- scratch (static device memory; no allocs allowed) ----------------
__device__ float  g_comb[NTOK*DOWND];      // combined expert outputs (fp32, atomic)
__device__ __half g_xh[NTOK*HID];          // x as fp16
__device__ __half g_wh[NE*DOWND*HID];      // down_w fp16
__device__ __half g_uh[HID*DOWND];         // up_w fp16
__device__ __half g_hh[NTOK*DOWND];        // gelu(combined) fp16
__device__ int   g_pair_tok[NPAIR];
__device__ float g_pair_w [NPAIR];
__device__ int   g_ei[NTOK*2];
__device__ float g_wp[NTOK*2];
__device__ int   g_cnt[NE];
__device__ int   g_off[NE];
__device__ int   g_tiles[1024];            // expert tile queue: (e<<10)|(mt<<2)|nt
__device__ int   g_ntiles;
__device__ int   g_tq;                     // queue head

// ---------------- PTX helpers (Ampere-class: valid on compute_103 base) ----------------
__device__ __forceinline__ uint32_t smem_u32(const void* p){
    uint32_t a;
    asm("{ .reg .u64 t; cvta.to.shared.u64 t, %1; cvt.u32.u64 %0, t; }" : "=r"(a) : "l"(p));
    return a;
}
__device__ __forceinline__ void cpa16(uint32_t saddr, const void* g){
    asm volatile("cp.async.cg.shared.global [%0], [%1], 16;" :: "r"(saddr), "l"(g));
}
__device__ __forceinline__ void ldm_x4(uint32_t* r, uint32_t addr){
    asm volatile("ldmatrix.sync.aligned.m8n8.x4.shared.b16 {%0,%1,%2,%3}, [%4];"
        : "=r"(r[0]), "=r"(r[1]), "=r"(r[2]), "=r"(r[3]) : "r"(addr));
}
__device__ __forceinline__ void mma16816(float* c, const uint32_t* a, const uint32_t* b){
    asm volatile("mma.sync.aligned.m16n8k16.row.col.f32.f16.f16.f32 "
        "{%0,%1,%2,%3}, {%4,%5,%6,%7}, {%8,%9}, {%0,%1,%2,%3};"
        : "+f"(c[0]), "+f"(c[1]), "+f"(c[2]), "+f"(c[3])
        : "r"(a[0]), "r"(a[1]), "r"(a[2]), "r"(a[3]), "r"(b[0]), "r"(b[1]));
}

__device__ __forceinline__ float gelu_new(float v){
    float c = v + 0.044715f * v * v * v;
    return 0.5f * v * (1.0f + tanhf(0.7978845608028654f * c));
}

// ---------------- fused preamble: gate + x->fp16, comb zero, weight cvt ----------------
#define N4_DW (NE*DOWND*HID/4)
#define N4_UW (HID*DOWND/4)
#define GATE_BLKS (NTOK/32)                          // 256
#define ZERO_BLKS (NTOK*DOWND/4/256)                 // 4096
#define CVT_BLKS  ((N4_DW + N4_UW + 255)/256)        // 17408
#define PRE_BLKS  (GATE_BLKS + ZERO_BLKS + CVT_BLKS)

__global__ void __launch_bounds__(256)
k_pre(const float* __restrict__ x, const float* __restrict__ gw,
      __half* __restrict__ xh,
      const float* __restrict__ dw, __half* __restrict__ wh,
      const float* __restrict__ uw, __half* __restrict__ uh,
      float* __restrict__ comb)
{
    int b = blockIdx.x;
    int tid = threadIdx.x;
    if (b < GATE_BLKS){
        // gate: 4 tokens per warp; writes logits-derived routing + x fp16
        int warp = tid >> 5;
        int lane = tid & 31;
        int n0 = (b * 8 + warp) * 4;
        const float4* x4 = (const float4*)x;
        const float4* g4 = (const float4*)gw;
        float acc[4][NE];
#pragma unroll
        for (int t = 0; t < 4; t++)
#pragma unroll
            for (int e = 0; e < NE; e++) acc[t][e] = 0.0f;
        for (int i = 0; i < 16; i++){
            int j = lane + 32*i;
            float4 xv[4];
#pragma unroll
            for (int t = 0; t < 4; t++){
                xv[t] = x4[(size_t)(n0+t)*(HID/4) + j];
                size_t o = (size_t)(n0+t)*HID + (size_t)j*4;
                ((__half2*)(xh + o))[0] = __floats2half2_rn(xv[t].x, xv[t].y);
                ((__half2*)(xh + o))[1] = __floats2half2_rn(xv[t].z, xv[t].w);
            }
#pragma unroll
            for (int e = 0; e < NE; e++){
                float4 gv = g4[e*(HID/4) + j];
#pragma unroll
                for (int t = 0; t < 4; t++)
                    acc[t][e] += xv[t].x*gv.x + xv[t].y*gv.y + xv[t].z*gv.z + xv[t].w*gv.w;
            }
        }
#pragma unroll
        for (int t = 0; t < 4; t++)
#pragma unroll
            for (int e = 0; e < NE; e++){
#pragma unroll
                for (int o = 16; o > 0; o >>= 1)
                    acc[t][e] += __shfl_xor_sync(0xffffffffu, acc[t][e], o);
            }
        if (lane == 0){
#pragma unroll
            for (int t = 0; t < 4; t++){
                int n = n0 + t;
                float v0 = -1e30f, v1 = -1e30f; int i0 = 0, i1 = 0;
#pragma unroll
                for (int e = 0; e < NE; e++){
                    float v = acc[t][e];
                    if (v > v0){ v1 = v0; i1 = i0; v0 = v; i0 = e; }
                    else if (v > v1){ v1 = v; i1 = e; }
                }
                float ee = expf(v1 - v0);
                float s  = 1.0f + ee;
                g_ei[2*n]   = i0; g_ei[2*n+1] = i1;
                g_wp[2*n]   = 1.0f / s; g_wp[2*n+1] = ee / s;
            }
        }
    } else if (b < GATE_BLKS + ZERO_BLKS){
        int i = (b - GATE_BLKS) * 256 + tid;
        ((float4*)comb)[i] = make_float4(0.f, 0.f, 0.f, 0.f);
    } else {
        int i = (b - GATE_BLKS - ZERO_BLKS) * 256 + tid;
        const float* in; __half* h; int idx;
        if (i < N4_DW){ in = dw; h = wh; idx = i; }
        else if (i < N4_DW + N4_UW){ in = uw; h = uh; idx = i - N4_DW; }
        else return;
        float4 v = ((const float4*)in)[idx];
        ((__half2*)h)[2*idx]   = __floats2half2_rn(v.x, v.y);
        ((__half2*)h)[2*idx+1] = __floats2half2_rn(v.z, v.w);
    }
}

// ---------------- fused routing: counts + loss + prefix + scatter + tile queue ----------------
__global__ void __launch_bounds__(256)
k_route(float* __restrict__ loss_out){
    __shared__ int   s_cnt[NE];
    __shared__ float s_sum[NE];
    __shared__ int   s_cur[NE];
    int tid = threadIdx.x;
    if (tid < NE){ s_cnt[tid] = 0; s_sum[tid] = 0.0f; }
    __syncthreads();
    for (int i = tid; i < NTOK*2; i += 256){
        int e = g_ei[i];
        atomicAdd(&s_cnt[e], 1);
        atomicAdd(&s_sum[e], g_wp[i]);
    }
    __syncthreads();
    if (tid == 0){
        int a = 0, nt = 0; float ls = 0.0f;
        for (int e = 0; e < NE; e++){
            s_cur[e] = a;
            g_off[e] = a;
            g_cnt[e] = s_cnt[e];
            int mts = (s_cnt[e] + 127) >> 7;
            for (int mt = 0; mt < mts; mt++)
                for (int n = 0; n < 4; n++)
                    g_tiles[nt++] = (e << 10) | (mt << 2) | n;
            a += s_cnt[e];
            float t = s_sum[e] / (float)NTOK;
            ls += t * t;
        }
        g_ntiles = nt;
        g_tq = 0;
        *loss_out = (float)NE * ls * 0.1f;
    }
    __syncthreads();
    for (int i = tid; i < NTOK*2; i += 256){
        int e = g_ei[i];
        int p = atomicAdd(&s_cur[e], 1);
        g_pair_tok[p] = i >> 1;
        g_pair_w [p]  = g_wp[i];
    }
}

// ---------------- GEMM configuration ----------------
// Block 128x128, BK=64, 4 warps (2x2), warp tile 64x64. 3-stage cp.async pipeline,
// intra-kt ldmatrix fragment double-buffering.
#define STAGE_BYTES 32768
#define OFF_A 0
#define OFF_B 16384
#define GSMEM  (3*STAGE_BYTES)
#define PS_BLOCKS 304   // 2 per SM (152 SMs on GB300; extras exit fast)

// ---------------- persistent expert GEMM (tile queue, fused scatter-add combine) ----------------
__global__ void __launch_bounds__(128, 2)
k_expert_ps(const __half* __restrict__ A, const __half* __restrict__ B,
            const float* __restrict__ bias, float* __restrict__ C)
{
    extern __shared__ char smem[];
    uint32_t sm = smem_u32(smem);
    __shared__ int s_aoff[128];
    __shared__ int s_atok[128];
    __shared__ int s_boff[128];
    __shared__ int s_tile;

    int tid  = threadIdx.x;
    int lane = tid & 31;
    int wid  = tid >> 5;
    int wm   = wid >> 1;
    int wn   = wid & 1;

    int arow0 = wm*64 + (lane & 15);
    int achk  = lane >> 4;
    int bgrp  = lane >> 3;
    int brow0 = wn*64 + (bgrp >> 1)*8 + (lane & 7);
    int bchk  = bgrp & 1;
    int gg    = lane >> 2;
    int tgi   = lane & 3;

    const int NK = HID / 64;   // 32

    while (true){
        if (tid == 0) s_tile = atomicAdd(&g_tq, 1);
        __syncthreads();
        int t = s_tile;
        if (t >= g_ntiles) break;

        int q   = g_tiles[t];
        int e   = q >> 10;
        int m0  = ((q >> 2) & 0xFF) * 128;
        int n0  = (q & 3) * 128;
        int cnt = g_cnt[e];
        int base= g_off[e];
        const float* bptr = bias + e*DOWND;

        {
            int m = m0 + tid;
            int ar = g_pair_tok[base + ((m < cnt) ? m : 0)];
            s_atok[tid] = ar;
            s_aoff[tid] = ar * HID;
            s_boff[tid] = (e*DOWND + n0 + tid) * HID;
        }
        __syncthreads();

        auto copy_stage = [&](int kt, int buf){
            uint32_t st = sm + buf*STAGE_BYTES;
            int kbase = kt*64;
            int c  = tid & 7;
            int rb = tid >> 3;
#pragma unroll
            for (int i = 0; i < 8; i++){
                int row = rb + i*16;
                uint32_t soff = (uint32_t)row*128u + (uint32_t)((c ^ (row & 7))<<4);
                cpa16(st + OFF_A + soff, A + s_aoff[row] + kbase + c*8);
            }
#pragma unroll
            for (int i = 0; i < 8; i++){
                int row = rb + i*16;
                uint32_t soff = (uint32_t)row*128u + (uint32_t)((c ^ (row & 7))<<4);
                cpa16(st + OFF_B + soff, B + s_boff[row] + kbase + c*8);
            }
        };

        copy_stage(0, 0);
        asm volatile("cp.async.commit_group;" ::: "memory");
        copy_stage(1, 1);
        asm volatile("cp.async.commit_group;" ::: "memory");
        copy_stage(2, 2);
        asm volatile("cp.async.commit_group;" ::: "memory");

        float acc[4][8][4];
#pragma unroll
        for (int a = 0; a < 4; a++)
#pragma unroll
            for (int bb = 0; bb < 8; bb++)
#pragma unroll
                for (int c = 0; c < 4; c++) acc[a][bb][c] = 0.0f;

        uint32_t fa[2][4][4], fb[2][4][4];
        auto load_frags = [&](int ks, uint32_t st, uint32_t (*fA)[4], uint32_t (*fB)[4]){
#pragma unroll
            for (int mt = 0; mt < 4; mt++){
                int r  = arow0 + mt*16;
                int ch = ks*2 + achk;
                uint32_t sa = (uint32_t)r*128u + (uint32_t)(((ch ^ (r & 7)) & 7)<<4);
                ldm_x4(fA[mt], st + OFF_A + sa);
            }
#pragma unroll
            for (int ntp = 0; ntp < 4; ntp++){
                int r  = brow0 + ntp*16;
                int ch = ks*2 + bchk;
                uint32_t sb = (uint32_t)r*128u + (uint32_t)(((ch ^ (r & 7)) & 7)<<4);
                ldm_x4(fB[ntp], st + OFF_B + sb);
            }
        };

        for (int kt = 0; kt < NK; kt++){
            if (kt + 2 < NK)      asm volatile("cp.async.wait_group 2;" ::: "memory");
            else if (kt + 1 < NK) asm volatile("cp.async.wait_group 1;" ::: "memory");
            else                  asm volatile("cp.async.wait_group 0;" ::: "memory");
            __syncthreads();

            uint32_t st = sm + (kt % 3)*STAGE_BYTES;
            load_frags(0, st, fa[0], fb[0]);
#pragma unroll
            for (int ks = 0; ks < 4; ks++){
                int cur = ks & 1;
                if (ks < 3) load_frags(ks + 1, st, fa[cur^1], fb[cur^1]);
#pragma unroll
                for (int ntp = 0; ntp < 4; ntp++){
#pragma unroll
                    for (int mt = 0; mt < 4; mt++){
                        mma16816(acc[mt][2*ntp  ], fa[cur][mt], fb[cur][ntp]    );
                        mma16816(acc[mt][2*ntp+1], fa[cur][mt], fb[cur][ntp] + 2);
                    }
                }
            }
            __syncthreads();
            if (kt + 3 < NK){
                copy_stage(kt + 3, (kt + 3) % 3);
                asm volatile("cp.async.commit_group;" ::: "memory");
            }
        }

        // epilogue: scatter-add w*(acc+bias) into combined buffer (2 addends per elem)
#pragma unroll
        for (int mt = 0; mt < 4; mt++){
#pragma unroll
            for (int h = 0; h < 2; h++){
                int r = wm*64 + mt*16 + gg + h*8;
                int m = m0 + r;
                if (m >= cnt) continue;
                float w = g_pair_w[base + m];
                size_t rowbase = (size_t)s_atok[r] * DOWND;
#pragma unroll
                for (int nt = 0; nt < 8; nt++){
                    int col = n0 + wn*64 + nt*8 + tgi*2;
                    float2 v;
                    v.x = (acc[mt][nt][2*h+0] + __ldg(bptr + col    )) * w;
                    v.y = (acc[mt][nt][2*h+1] + __ldg(bptr + col + 1)) * w;
                    atomicAdd((float2*)&C[rowbase + col], v);
                }
            }
        }
    }
}

// ---------------- up-projection GEMM (static grid) ----------------
__global__ void __launch_bounds__(128, 2)
k_up(const __half* __restrict__ A, const __half* __restrict__ B,
     const float* __restrict__ bias, float* __restrict__ C)
{
    int m0 = blockIdx.x * 128;
    int n0 = blockIdx.y * 128;

    extern __shared__ char smem[];
    uint32_t sm = smem_u32(smem);
    __shared__ int s_aoff[128];
    __shared__ int s_boff[128];

    int tid  = threadIdx.x;
    int lane = tid & 31;
    int wid  = tid >> 5;
    int wm   = wid >> 1;
    int wn   = wid & 1;

    s_aoff[tid] = (m0 + tid) * DOWND;
    s_boff[tid] = (n0 + tid) * DOWND;
    __syncthreads();

    const int NK = DOWND / 64;   // 8

    auto copy_stage = [&](int kt, int buf){
        uint32_t st = sm + buf*STAGE_BYTES;
        int kbase = kt*64;
        int c  = tid & 7;
        int rb = tid >> 3;
#pragma unroll
        for (int i = 0; i < 8; i++){
            int row = rb + i*16;
            uint32_t soff = (uint32_t)row*128u + (uint32_t)((c ^ (row & 7))<<4);
            cpa16(st + OFF_A + soff, A + s_aoff[row] + kbase + c*8);
        }
#pragma unroll
        for (int i = 0; i < 8; i++){
            int row = rb + i*16;
            uint32_t soff = (uint32_t)row*128u + (uint32_t)((c ^ (row & 7))<<4);
            cpa16(st + OFF_B + soff, B + s_boff[row] + kbase + c*8);
        }
    };

    copy_stage(0, 0);
    asm volatile("cp.async.commit_group;" ::: "memory");
    copy_stage(1, 1);
    asm volatile("cp.async.commit_group;" ::: "memory");
    copy_stage(2, 2);
    asm volatile("cp.async.commit_group;" ::: "memory");

    float acc[4][8][4];
#pragma unroll
    for (int a = 0; a < 4; a++)
#pragma unroll
        for (int b = 0; b < 8; b++)
#pragma unroll
            for (int c = 0; c < 4; c++) acc[a][b][c] = 0.0f;

    int arow0 = wm*64 + (lane & 15);
    int achk  = lane >> 4;
    int bgrp  = lane >> 3;
    int brow0 = wn*64 + (bgrp >> 1)*8 + (lane & 7);
    int bchk  = bgrp & 1;

    uint32_t fa[2][4][4], fb[2][4][4];
    auto load_frags = [&](int ks, uint32_t st, uint32_t (*fA)[4], uint32_t (*fB)[4]){
#pragma unroll
        for (int mt = 0; mt < 4; mt++){
            int r  = arow0 + mt*16;
            int ch = ks*2 + achk;
            uint32_t sa = (uint32_t)r*128u + (uint32_t)(((ch ^ (r & 7)) & 7)<<4);
            ldm_x4(fA[mt], st + OFF_A + sa);
        }
#pragma unroll
        for (int ntp = 0; ntp < 4; ntp++){
            int r  = brow0 + ntp*16;
            int ch = ks*2 + bchk;
            uint32_t sb = (uint32_t)r*128u + (uint32_t)(((ch ^ (r & 7)) & 7)<<4);
            ldm_x4(fB[ntp], st + OFF_B + sb);
        }
    };

    for (int kt = 0; kt < NK; kt++){
        if (kt + 2 < NK)      asm volatile("cp.async.wait_group 2;" ::: "memory");
        else if (kt + 1 < NK) asm volatile("cp.async.wait_group 1;" ::: "memory");
        else                  asm volatile("cp.async.wait_group 0;" ::: "memory");
        __syncthreads();

        uint32_t st = sm + (kt % 3)*STAGE_BYTES;
        load_frags(0, st, fa[0], fb[0]);
#pragma unroll
        for (int ks = 0; ks < 4; ks++){
            int cur = ks & 1;
            if (ks < 3) load_frags(ks + 1, st, fa[cur^1], fb[cur^1]);
#pragma unroll
            for (int ntp = 0; ntp < 4; ntp++){
#pragma unroll
                for (int mt = 0; mt < 4; mt++){
                    mma16816(acc[mt][2*ntp  ], fa[cur][mt], fb[cur][ntp]    );
                    mma16816(acc[mt][2*ntp+1], fa[cur][mt], fb[cur][ntp] + 2);
                }
            }
        }
        __syncthreads();
        if (kt + 3 < NK){
            copy_stage(kt + 3, (kt + 3) % 3);
            asm volatile("cp.async.commit_group;" ::: "memory");
        }
    }

    int g   = lane >> 2;
    int tgi = lane & 3;
#pragma unroll
    for (int mt = 0; mt < 4; mt++){
#pragma unroll
        for (int h = 0; h < 2; h++){
            int r = wm*64 + mt*16 + g + h*8;
            size_t rowbase = (size_t)(m0 + r) * HID;
#pragma unroll
            for (int nt = 0; nt < 8; nt++){
                int col = n0 + wn*64 + nt*8 + tgi*2;
                float2 v;
                v.x = acc[mt][nt][2*h+0] + __ldg(bias + col    );
                v.y = acc[mt][nt][2*h+1] + __ldg(bias + col + 1);
                *(float2*)&C[rowbase + col] = v;
            }
        }
    }
}

// ---------------- gelu over combined buffer -> fp16 ----------------
__global__ void k_combine(const float* __restrict__ comb, __half* __restrict__ hh){
    int i = blockIdx.x * blockDim.x + threadIdx.x;
    float4 v = ((const float4*)comb)[i];
    float g0 = gelu_new(v.x);
    float g1 = gelu_new(v.y);
    float g2 = gelu_new(v.z);
    float g3 = gelu_new(v.w);
    ((__half2*)hh)[2*i]   = __floats2half2_rn(g0, g1);
    ((__half2*)hh)[2*i+1] = __floats2half2_rn(g2, g3);
}

// ---------------- launch ----------------
extern "C" void kernel_launch(void* const* d_in, const int* in_sizes, int n_in,
                              void* d_out, int out_size){
    const float* x      = (const float*)d_in[0];
    const float* gate_w = (const float*)d_in[1];
    const float* down_w = (const float*)d_in[2];
    const float* down_b = (const float*)d_in[3];
    const float* up_w   = (const float*)d_in[4];
    const float* up_b   = (const float*)d_in[5];
    float* out = (float*)d_out;

    void *p_xh, *p_wh, *p_uh, *p_hh, *p_comb;
    cudaGetSymbolAddress(&p_xh,   g_xh);
    cudaGetSymbolAddress(&p_wh,   g_wh);
    cudaGetSymbolAddress(&p_uh,   g_uh);
    cudaGetSymbolAddress(&p_hh,   g_hh);
    cudaGetSymbolAddress(&p_comb, g_comb);

    cudaFuncSetAttribute(k_expert_ps, cudaFuncAttributeMaxDynamicSharedMemorySize, GSMEM);
    cudaFuncSetAttribute(k_up,        cudaFuncAttributeMaxDynamicSharedMemorySize, GSMEM);

    // fused preamble: gate (+x fp16), comb zero, weight fp16 conversions — one launch
    k_pre<<<PRE_BLKS, 256>>>(x, gate_w, (__half*)p_xh,
                             down_w, (__half*)p_wh,
                             up_w,   (__half*)p_uh,
                             (float*)p_comb);

    // fused routing: counts + prefix + loss + scatter + tile queue
    k_route<<<1, 256>>>(out + (size_t)NTOK * HID);

    // persistent grouped expert GEMM with fused scatter-add combine
    k_expert_ps<<<PS_BLOCKS, 128, GSMEM>>>(
        (const __half*)p_xh, (const __half*)p_wh, down_b, (float*)p_comb);

    k_combine<<<(NTOK*DOWND/4)/256, 256>>>((const float*)p_comb, (__half*)p_hh);

    // up projection: out = h . up_w^T + up_b
    dim3 gu(NTOK/128, HID/128);
    k_up<<<gu, 128, GSMEM>>>(
        (const __half*)p_hh, (const __half*)p_uh, up_b, out);
}

// round 14
// speedup vs baseline: 1.1175x; 1.1175x over previous
#include <cuda_runtime.h>
#include <cuda_fp16.h>
#include <math.h>
#include <stdint.h>

#define HID   2048
#define DOWND 512
#define NE    16
#define NTOK  8192
#define NPAIR (NTOK*2)

// ---------------- scratch (static device memory; no allocs allowed) ----------------
__device__ float  g_comb[NTOK*DOWND];      // combined expert outputs (fp32, atomic)
__device__ __half g_xh[NTOK*HID];          // x as fp16
__device__ __half g_wh[NE*DOWND*HID];      // down_w fp16
__device__ __half g_uh[HID*DOWND];         // up_w fp16
__device__ __half g_hh[NTOK*DOWND];        // gelu(combined) fp16
__device__ int   g_pair_tok[NPAIR];
__device__ float g_pair_w [NPAIR];
__device__ int   g_ei[NTOK*2];
__device__ float g_wp[NTOK*2];
__device__ int   g_cnt[NE];
__device__ int   g_off[NE];
__device__ int   g_tiles[1024];            // expert tile queue: (e<<10)|(mt<<2)|nt
__device__ int   g_ntiles;
__device__ int   g_tq;                     // queue head

// ---------------- PTX helpers (Ampere-class: valid on compute_103 base) ----------------
__device__ __forceinline__ uint32_t smem_u32(const void* p){
    uint32_t a;
    asm("{ .reg .u64 t; cvta.to.shared.u64 t, %1; cvt.u32.u64 %0, t; }" : "=r"(a) : "l"(p));
    return a;
}
__device__ __forceinline__ void cpa16(uint32_t saddr, const void* g){
    asm volatile("cp.async.cg.shared.global [%0], [%1], 16;" :: "r"(saddr), "l"(g));
}
__device__ __forceinline__ void ldm_x4(uint32_t* r, uint32_t addr){
    asm volatile("ldmatrix.sync.aligned.m8n8.x4.shared.b16 {%0,%1,%2,%3}, [%4];"
        : "=r"(r[0]), "=r"(r[1]), "=r"(r[2]), "=r"(r[3]) : "r"(addr));
}
__device__ __forceinline__ void mma16816(float* c, const uint32_t* a, const uint32_t* b){
    asm volatile("mma.sync.aligned.m16n8k16.row.col.f32.f16.f16.f32 "
        "{%0,%1,%2,%3}, {%4,%5,%6,%7}, {%8,%9}, {%0,%1,%2,%3};"
        : "+f"(c[0]), "+f"(c[1]), "+f"(c[2]), "+f"(c[3])
        : "r"(a[0]), "r"(a[1]), "r"(a[2]), "r"(a[3]), "r"(b[0]), "r"(b[1]));
}

__device__ __forceinline__ float gelu_new(float v){
    float c = v + 0.044715f * v * v * v;
    return 0.5f * v * (1.0f + tanhf(0.7978845608028654f * c));
}

// ---------------- zero combine buffer (low-reg, high-occupancy) ----------------
__global__ void k_zero(float* __restrict__ c){
    int i = blockIdx.x * blockDim.x + threadIdx.x;
    ((float4*)c)[i] = make_float4(0.f, 0.f, 0.f, 0.f);
}

// ---------------- gate: 4 tokens per warp; writes routing + x fp16 (no atomics) --------
__global__ void k_gate(const float* __restrict__ x, const float* __restrict__ gw,
                       __half* __restrict__ xh){
    int warp = threadIdx.x >> 5;
    int lane = threadIdx.x & 31;
    int n0 = (blockIdx.x * 8 + warp) * 4;      // 4 tokens per warp
    const float4* x4 = (const float4*)x;
    const float4* g4 = (const float4*)gw;
    float acc[4][NE];
#pragma unroll
    for (int t = 0; t < 4; t++)
#pragma unroll
        for (int e = 0; e < NE; e++) acc[t][e] = 0.0f;

    for (int i = 0; i < 16; i++){
        int j = lane + 32*i;
        float4 xv[4];
#pragma unroll
        for (int t = 0; t < 4; t++){
            xv[t] = x4[(size_t)(n0+t)*(HID/4) + j];
            size_t o = (size_t)(n0+t)*HID + (size_t)j*4;
            ((__half2*)(xh + o))[0] = __floats2half2_rn(xv[t].x, xv[t].y);
            ((__half2*)(xh + o))[1] = __floats2half2_rn(xv[t].z, xv[t].w);
        }
#pragma unroll
        for (int e = 0; e < NE; e++){
            float4 gv = g4[e*(HID/4) + j];
#pragma unroll
            for (int t = 0; t < 4; t++)
                acc[t][e] += xv[t].x*gv.x + xv[t].y*gv.y + xv[t].z*gv.z + xv[t].w*gv.w;
        }
    }
#pragma unroll
    for (int t = 0; t < 4; t++)
#pragma unroll
        for (int e = 0; e < NE; e++){
#pragma unroll
            for (int o = 16; o > 0; o >>= 1)
                acc[t][e] += __shfl_xor_sync(0xffffffffu, acc[t][e], o);
        }
    if (lane == 0){
#pragma unroll
        for (int t = 0; t < 4; t++){
            int n = n0 + t;
            float v0 = -1e30f, v1 = -1e30f; int i0 = 0, i1 = 0;
#pragma unroll
            for (int e = 0; e < NE; e++){
                float v = acc[t][e];
                if (v > v0){ v1 = v0; i1 = i0; v0 = v; i0 = e; }
                else if (v > v1){ v1 = v; i1 = e; }
            }
            float ee = expf(v1 - v0);
            float s  = 1.0f + ee;
            g_ei[2*n]   = i0; g_ei[2*n+1] = i1;
            g_wp[2*n]   = 1.0f / s; g_wp[2*n+1] = ee / s;
        }
    }
}

// ---------------- fused routing: counts + loss + prefix + scatter + tile queue --------
__global__ void __launch_bounds__(256)
k_route(float* __restrict__ loss_out){
    __shared__ int   s_cnt[NE];
    __shared__ float s_sum[NE];
    __shared__ int   s_cur[NE];
    int tid = threadIdx.x;
    if (tid < NE){ s_cnt[tid] = 0; s_sum[tid] = 0.0f; }
    __syncthreads();
    for (int i = tid; i < NTOK*2; i += 256){
        int e = g_ei[i];
        atomicAdd(&s_cnt[e], 1);
        atomicAdd(&s_sum[e], g_wp[i]);
    }
    __syncthreads();
    if (tid == 0){
        int a = 0, nt = 0; float ls = 0.0f;
        for (int e = 0; e < NE; e++){
            s_cur[e] = a;
            g_off[e] = a;
            g_cnt[e] = s_cnt[e];
            int mts = (s_cnt[e] + 127) >> 7;
            for (int mt = 0; mt < mts; mt++)
                for (int n = 0; n < 4; n++)
                    g_tiles[nt++] = (e << 10) | (mt << 2) | n;
            a += s_cnt[e];
            float t = s_sum[e] / (float)NTOK;
            ls += t * t;
        }
        g_ntiles = nt;
        g_tq = 0;
        *loss_out = (float)NE * ls * 0.1f;
    }
    __syncthreads();
    for (int i = tid; i < NTOK*2; i += 256){
        int e = g_ei[i];
        int p = atomicAdd(&s_cur[e], 1);
        g_pair_tok[p] = i >> 1;
        g_pair_w [p]  = g_wp[i];
    }
}

// ---------------- fp32 -> fp16 conversion (both weight tensors; low-reg kernel) -------
#define N4_DW (NE*DOWND*HID/4)
#define N4_UW (HID*DOWND/4)
__global__ void k_cvt1(const float* __restrict__ dw, __half* __restrict__ wh,
                       const float* __restrict__ uw, __half* __restrict__ uh){
    int i = blockIdx.x * blockDim.x + threadIdx.x;
    const float* in; __half* h; int idx;
    if (i < N4_DW){ in = dw; h = wh; idx = i; }
    else if (i < N4_DW + N4_UW){ in = uw; h = uh; idx = i - N4_DW; }
    else return;
    float4 v = ((const float4*)in)[idx];
    ((__half2*)h)[2*idx]   = __floats2half2_rn(v.x, v.y);
    ((__half2*)h)[2*idx+1] = __floats2half2_rn(v.z, v.w);
}

// ---------------- GEMM configuration ----------------
// Block 128x128, BK=64, 4 warps (2x2), warp tile 64x64. 3-stage cp.async pipeline,
// intra-kt ldmatrix fragment double-buffering.
#define STAGE_BYTES 32768
#define OFF_A 0
#define OFF_B 16384
#define GSMEM  (3*STAGE_BYTES)
#define PS_BLOCKS 304   // 2 per SM; extras exit fast

// ---------------- persistent expert GEMM (tile queue, fused scatter-add combine) ------
__global__ void __launch_bounds__(128, 2)
k_expert_ps(const __half* __restrict__ A, const __half* __restrict__ B,
            const float* __restrict__ bias, float* __restrict__ C)
{
    extern __shared__ char smem[];
    uint32_t sm = smem_u32(smem);
    __shared__ int s_aoff[128];
    __shared__ int s_atok[128];
    __shared__ int s_boff[128];
    __shared__ int s_tile;

    int tid  = threadIdx.x;
    int lane = tid & 31;
    int wid  = tid >> 5;
    int wm   = wid >> 1;
    int wn   = wid & 1;

    int arow0 = wm*64 + (lane & 15);
    int achk  = lane >> 4;
    int bgrp  = lane >> 3;
    int brow0 = wn*64 + (bgrp >> 1)*8 + (lane & 7);
    int bchk  = bgrp & 1;
    int gg    = lane >> 2;
    int tgi   = lane & 3;

    const int NK = HID / 64;   // 32

    while (true){
        if (tid == 0) s_tile = atomicAdd(&g_tq, 1);
        __syncthreads();
        int t = s_tile;
        if (t >= g_ntiles) break;

        int q   = g_tiles[t];
        int e   = q >> 10;
        int m0  = ((q >> 2) & 0xFF) * 128;
        int n0  = (q & 3) * 128;
        int cnt = g_cnt[e];
        int base= g_off[e];
        const float* bptr = bias + e*DOWND;

        {
            int m = m0 + tid;
            int ar = g_pair_tok[base + ((m < cnt) ? m : 0)];
            s_atok[tid] = ar;
            s_aoff[tid] = ar * HID;
            s_boff[tid] = (e*DOWND + n0 + tid) * HID;
        }
        __syncthreads();

        auto copy_stage = [&](int kt, int buf){
            uint32_t st = sm + buf*STAGE_BYTES;
            int kbase = kt*64;
            int c  = tid & 7;
            int rb = tid >> 3;
#pragma unroll
            for (int i = 0; i < 8; i++){
                int row = rb + i*16;
                uint32_t soff = (uint32_t)row*128u + (uint32_t)((c ^ (row & 7))<<4);
                cpa16(st + OFF_A + soff, A + s_aoff[row] + kbase + c*8);
            }
#pragma unroll
            for (int i = 0; i < 8; i++){
                int row = rb + i*16;
                uint32_t soff = (uint32_t)row*128u + (uint32_t)((c ^ (row & 7))<<4);
                cpa16(st + OFF_B + soff, B + s_boff[row] + kbase + c*8);
            }
        };

        copy_stage(0, 0);
        asm volatile("cp.async.commit_group;" ::: "memory");
        copy_stage(1, 1);
        asm volatile("cp.async.commit_group;" ::: "memory");
        copy_stage(2, 2);
        asm volatile("cp.async.commit_group;" ::: "memory");

        float acc[4][8][4];
#pragma unroll
        for (int a = 0; a < 4; a++)
#pragma unroll
            for (int bb = 0; bb < 8; bb++)
#pragma unroll
                for (int c = 0; c < 4; c++) acc[a][bb][c] = 0.0f;

        uint32_t fa[2][4][4], fb[2][4][4];
        auto load_frags = [&](int ks, uint32_t st, uint32_t (*fA)[4], uint32_t (*fB)[4]){
#pragma unroll
            for (int mt = 0; mt < 4; mt++){
                int r  = arow0 + mt*16;
                int ch = ks*2 + achk;
                uint32_t sa = (uint32_t)r*128u + (uint32_t)(((ch ^ (r & 7)) & 7)<<4);
                ldm_x4(fA[mt], st + OFF_A + sa);
            }
#pragma unroll
            for (int ntp = 0; ntp < 4; ntp++){
                int r  = brow0 + ntp*16;
                int ch = ks*2 + bchk;
                uint32_t sb = (uint32_t)r*128u + (uint32_t)(((ch ^ (r & 7)) & 7)<<4);
                ldm_x4(fB[ntp], st + OFF_B + sb);
            }
        };

        for (int kt = 0; kt < NK; kt++){
            if (kt + 2 < NK)      asm volatile("cp.async.wait_group 2;" ::: "memory");
            else if (kt + 1 < NK) asm volatile("cp.async.wait_group 1;" ::: "memory");
            else                  asm volatile("cp.async.wait_group 0;" ::: "memory");
            __syncthreads();

            uint32_t st = sm + (kt % 3)*STAGE_BYTES;
            load_frags(0, st, fa[0], fb[0]);
#pragma unroll
            for (int ks = 0; ks < 4; ks++){
                int cur = ks & 1;
                if (ks < 3) load_frags(ks + 1, st, fa[cur^1], fb[cur^1]);
#pragma unroll
                for (int ntp = 0; ntp < 4; ntp++){
#pragma unroll
                    for (int mt = 0; mt < 4; mt++){
                        mma16816(acc[mt][2*ntp  ], fa[cur][mt], fb[cur][ntp]    );
                        mma16816(acc[mt][2*ntp+1], fa[cur][mt], fb[cur][ntp] + 2);
                    }
                }
            }
            __syncthreads();
            if (kt + 3 < NK){
                copy_stage(kt + 3, (kt + 3) % 3);
                asm volatile("cp.async.commit_group;" ::: "memory");
            }
        }

        // epilogue: scatter-add w*(acc+bias) into combined buffer (2 addends per elem,
        // zeroed buffer -> order-independent fp32 result)
#pragma unroll
        for (int mt = 0; mt < 4; mt++){
#pragma unroll
            for (int h = 0; h < 2; h++){
                int r = wm*64 + mt*16 + gg + h*8;
                int m = m0 + r;
                if (m >= cnt) continue;
                float w = g_pair_w[base + m];
                size_t rowbase = (size_t)s_atok[r] * DOWND;
#pragma unroll
                for (int nt = 0; nt < 8; nt++){
                    int col = n0 + wn*64 + nt*8 + tgi*2;
                    float2 v;
                    v.x = (acc[mt][nt][2*h+0] + __ldg(bptr + col    )) * w;
                    v.y = (acc[mt][nt][2*h+1] + __ldg(bptr + col + 1)) * w;
                    atomicAdd((float2*)&C[rowbase + col], v);
                }
            }
        }
    }
}

// ---------------- up-projection GEMM (static grid) ----------------
__global__ void __launch_bounds__(128, 2)
k_up(const __half* __restrict__ A, const __half* __restrict__ B,
     const float* __restrict__ bias, float* __restrict__ C)
{
    int m0 = blockIdx.x * 128;
    int n0 = blockIdx.y * 128;

    extern __shared__ char smem[];
    uint32_t sm = smem_u32(smem);
    __shared__ int s_aoff[128];
    __shared__ int s_boff[128];

    int tid  = threadIdx.x;
    int lane = tid & 31;
    int wid  = tid >> 5;
    int wm   = wid >> 1;
    int wn   = wid & 1;

    s_aoff[tid] = (m0 + tid) * DOWND;
    s_boff[tid] = (n0 + tid) * DOWND;
    __syncthreads();

    const int NK = DOWND / 64;   // 8

    auto copy_stage = [&](int kt, int buf){
        uint32_t st = sm + buf*STAGE_BYTES;
        int kbase = kt*64;
        int c  = tid & 7;
        int rb = tid >> 3;
#pragma unroll
        for (int i = 0; i < 8; i++){
            int row = rb + i*16;
            uint32_t soff = (uint32_t)row*128u + (uint32_t)((c ^ (row & 7))<<4);
            cpa16(st + OFF_A + soff, A + s_aoff[row] + kbase + c*8);
        }
#pragma unroll
        for (int i = 0; i < 8; i++){
            int row = rb + i*16;
            uint32_t soff = (uint32_t)row*128u + (uint32_t)((c ^ (row & 7))<<4);
            cpa16(st + OFF_B + soff, B + s_boff[row] + kbase + c*8);
        }
    };

    copy_stage(0, 0);
    asm volatile("cp.async.commit_group;" ::: "memory");
    copy_stage(1, 1);
    asm volatile("cp.async.commit_group;" ::: "memory");
    copy_stage(2, 2);
    asm volatile("cp.async.commit_group;" ::: "memory");

    float acc[4][8][4];
#pragma unroll
    for (int a = 0; a < 4; a++)
#pragma unroll
        for (int b = 0; b < 8; b++)
#pragma unroll
            for (int c = 0; c < 4; c++) acc[a][b][c] = 0.0f;

    int arow0 = wm*64 + (lane & 15);
    int achk  = lane >> 4;
    int bgrp  = lane >> 3;
    int brow0 = wn*64 + (bgrp >> 1)*8 + (lane & 7);
    int bchk  = bgrp & 1;

    uint32_t fa[2][4][4], fb[2][4][4];
    auto load_frags = [&](int ks, uint32_t st, uint32_t (*fA)[4], uint32_t (*fB)[4]){
#pragma unroll
        for (int mt = 0; mt < 4; mt++){
            int r  = arow0 + mt*16;
            int ch = ks*2 + achk;
            uint32_t sa = (uint32_t)r*128u + (uint32_t)(((ch ^ (r & 7)) & 7)<<4);
            ldm_x4(fA[mt], st + OFF_A + sa);
        }
#pragma unroll
        for (int ntp = 0; ntp < 4; ntp++){
            int r  = brow0 + ntp*16;
            int ch = ks*2 + bchk;
            uint32_t sb = (uint32_t)r*128u + (uint32_t)(((ch ^ (r & 7)) & 7)<<4);
            ldm_x4(fB[ntp], st + OFF_B + sb);
        }
    };

    for (int kt = 0; kt < NK; kt++){
        if (kt + 2 < NK)      asm volatile("cp.async.wait_group 2;" ::: "memory");
        else if (kt + 1 < NK) asm volatile("cp.async.wait_group 1;" ::: "memory");
        else                  asm volatile("cp.async.wait_group 0;" ::: "memory");
        __syncthreads();

        uint32_t st = sm + (kt % 3)*STAGE_BYTES;
        load_frags(0, st, fa[0], fb[0]);
#pragma unroll
        for (int ks = 0; ks < 4; ks++){
            int cur = ks & 1;
            if (ks < 3) load_frags(ks + 1, st, fa[cur^1], fb[cur^1]);
#pragma unroll
            for (int ntp = 0; ntp < 4; ntp++){
#pragma unroll
                for (int mt = 0; mt < 4; mt++){
                    mma16816(acc[mt][2*ntp  ], fa[cur][mt], fb[cur][ntp]    );
                    mma16816(acc[mt][2*ntp+1], fa[cur][mt], fb[cur][ntp] + 2);
                }
            }
        }
        __syncthreads();
        if (kt + 3 < NK){
            copy_stage(kt + 3, (kt + 3) % 3);
            asm volatile("cp.async.commit_group;" ::: "memory");
        }
    }

    int g   = lane >> 2;
    int tgi = lane & 3;
#pragma unroll
    for (int mt = 0; mt < 4; mt++){
#pragma unroll
        for (int h = 0; h < 2; h++){
            int r = wm*64 + mt*16 + g + h*8;
            size_t rowbase = (size_t)(m0 + r) * HID;
#pragma unroll
            for (int nt = 0; nt < 8; nt++){
                int col = n0 + wn*64 + nt*8 + tgi*2;
                float2 v;
                v.x = acc[mt][nt][2*h+0] + __ldg(bias + col    );
                v.y = acc[mt][nt][2*h+1] + __ldg(bias + col + 1);
                *(float2*)&C[rowbase + col] = v;
            }
        }
    }
}

// ---------------- gelu over combined buffer -> fp16 ----------------
__global__ void k_combine(const float* __restrict__ comb, __half* __restrict__ hh){
    int i = blockIdx.x * blockDim.x + threadIdx.x;
    float4 v = ((const float4*)comb)[i];
    float g0 = gelu_new(v.x);
    float g1 = gelu_new(v.y);
    float g2 = gelu_new(v.z);
    float g3 = gelu_new(v.w);
    ((__half2*)hh)[2*i]   = __floats2half2_rn(g0, g1);
    ((__half2*)hh)[2*i+1] = __floats2half2_rn(g2, g3);
}

// ---------------- launch ----------------
extern "C" void kernel_launch(void* const* d_in, const int* in_sizes, int n_in,
                              void* d_out, int out_size){
    const float* x      = (const float*)d_in[0];
    const float* gate_w = (const float*)d_in[1];
    const float* down_w = (const float*)d_in[2];
    const float* down_b = (const float*)d_in[3];
    const float* up_w   = (const float*)d_in[4];
    const float* up_b   = (const float*)d_in[5];
    float* out = (float*)d_out;

    void *p_xh, *p_wh, *p_uh, *p_hh, *p_comb;
    cudaGetSymbolAddress(&p_xh,   g_xh);
    cudaGetSymbolAddress(&p_wh,   g_wh);
    cudaGetSymbolAddress(&p_uh,   g_uh);
    cudaGetSymbolAddress(&p_hh,   g_hh);
    cudaGetSymbolAddress(&p_comb, g_comb);

    cudaFuncSetAttribute(k_expert_ps, cudaFuncAttributeMaxDynamicSharedMemorySize, GSMEM);
    cudaFuncSetAttribute(k_up,        cudaFuncAttributeMaxDynamicSharedMemorySize, GSMEM);

    // separate low-register preamble kernels (R13's fusion regressed: register union)
    k_zero<<<(NTOK*DOWND/4)/256, 256>>>((float*)p_comb);
    k_gate<<<NTOK/32, 256>>>(x, gate_w, (__half*)p_xh);
    k_route<<<1, 256>>>(out + (size_t)NTOK * HID);   // counts+prefix+loss+scatter+tiles
    k_cvt1<<<(N4_DW + N4_UW + 255)/256, 256>>>(down_w, (__half*)p_wh, up_w, (__half*)p_uh);

    // persistent grouped expert GEMM with fused scatter-add combine
    k_expert_ps<<<PS_BLOCKS, 128, GSMEM>>>(
        (const __half*)p_xh, (const __half*)p_wh, down_b, (float*)p_comb);

    k_combine<<<(NTOK*DOWND/4)/256, 256>>>((const float*)p_comb, (__half*)p_hh);

    // up projection: out = h . up_w^T + up_b
    dim3 gu(NTOK/128, HID/128);
    k_up<<<gu, 128, GSMEM>>>(
        (const __half*)p_hh, (const __half*)p_uh, up_b, out);
}